// round 1
// baseline (speedup 1.0000x reference)
#include <cuda_runtime.h>
#include <cuda_bf16.h>

#define SS 4096
#define CC 256
#define BB 2
#define NHH 4
#define HDD 64
#define NGROUPS 32
#define CPG 8
#define SCALE 0.0625f  // 1/sqrt(256)

// scratch (allocation-free rule: __device__ globals)
__device__ float g_norm[BB*CC*SS];
__device__ float g_q[BB*CC*SS];
__device__ float g_k[BB*CC*SS];
__device__ float g_v[BB*CC*SS];
__device__ float g_att[BB*CC*SS];

// ---------------- GroupNorm ----------------
__global__ void __launch_bounds__(256) gn_kernel(const float* __restrict__ x,
                                                 const float* __restrict__ w,
                                                 const float* __restrict__ b) {
    int grp = blockIdx.x;                       // b*32 + g
    const float* xp = x + (size_t)grp * CPG * SS;
    float* op = g_norm + (size_t)grp * CPG * SS;
    int t = threadIdx.x;
    const int n4 = CPG * SS / 4;                // 8192 float4s
    const float4* x4 = (const float4*)xp;
    float s0 = 0.f, s1 = 0.f;
    for (int i = t; i < n4; i += 256) {
        float4 v = x4[i];
        s0 += v.x + v.y + v.z + v.w;
        s1 += v.x*v.x + v.y*v.y + v.z*v.z + v.w*v.w;
    }
    __shared__ float r0[256], r1[256];
    r0[t] = s0; r1[t] = s1; __syncthreads();
    for (int o = 128; o > 0; o >>= 1) {
        if (t < o) { r0[t] += r0[t+o]; r1[t] += r1[t+o]; }
        __syncthreads();
    }
    __shared__ float mu_s, rs_s;
    if (t == 0) {
        float inv_n = 1.0f / (CPG * SS);
        float mu = r0[0] * inv_n;
        float var = r1[0] * inv_n - mu * mu;
        mu_s = mu;
        rs_s = rsqrtf(var + 1e-5f);
    }
    __syncthreads();
    float mu = mu_s, rs = rs_s;
    int g = grp % NGROUPS;
    float4* o4 = (float4*)op;
    for (int i = t; i < n4; i += 256) {
        int c = g * CPG + (i * 4) / SS;        // 4 elems share channel (SS%4==0)
        float wc = w[c], bc = b[c];
        float4 v = x4[i];
        v.x = (v.x - mu) * rs * wc + bc;
        v.y = (v.y - mu) * rs * wc + bc;
        v.z = (v.z - mu) * rs * wc + bc;
        v.w = (v.w - mu) * rs * wc + bc;
        o4[i] = v;
    }
}

// ---------------- Tiled SGEMM body (64x64 tile, 4x4 micro, BK=16) ----------------
// C[m0+i][j0+j] = sum_k A[m][k]*Bm[k][j];  A: [256][256], Bm: [256][SS]
__device__ __forceinline__ void gemm_tile(const float* __restrict__ A,
                                          const float* __restrict__ Bm,
                                          float acc[4][4],
                                          float (*a_s)[68], float (*b_s)[68],
                                          int m0, int j0, int t, int tx, int ty) {
    for (int k0 = 0; k0 < CC; k0 += 16) {
        {
            int m = t >> 2, kq = (t & 3) * 4;
            float4 av = *(const float4*)&A[(size_t)(m0 + m) * CC + k0 + kq];
            a_s[kq+0][m] = av.x; a_s[kq+1][m] = av.y;
            a_s[kq+2][m] = av.z; a_s[kq+3][m] = av.w;
            int kk = t >> 4, j4 = t & 15;
            float4 bv = *(const float4*)&Bm[(size_t)(k0 + kk) * SS + j0 + j4 * 4];
            *(float4*)&b_s[kk][j4 * 4] = bv;
        }
        __syncthreads();
        #pragma unroll
        for (int kk = 0; kk < 16; kk++) {
            float4 a = *(float4*)&a_s[kk][ty * 4];
            float4 bv = *(float4*)&b_s[kk][tx * 4];
            acc[0][0] += a.x * bv.x; acc[0][1] += a.x * bv.y; acc[0][2] += a.x * bv.z; acc[0][3] += a.x * bv.w;
            acc[1][0] += a.y * bv.x; acc[1][1] += a.y * bv.y; acc[1][2] += a.y * bv.z; acc[1][3] += a.y * bv.w;
            acc[2][0] += a.z * bv.x; acc[2][1] += a.z * bv.y; acc[2][2] += a.z * bv.z; acc[2][3] += a.z * bv.w;
            acc[3][0] += a.w * bv.x; acc[3][1] += a.w * bv.y; acc[3][2] += a.w * bv.z; acc[3][3] += a.w * bv.w;
        }
        __syncthreads();
    }
}

// ---------------- QKV projection ----------------
__global__ void __launch_bounds__(256) qkv_kernel(const float* __restrict__ wq,
                                                  const float* __restrict__ wk,
                                                  const float* __restrict__ wv) {
    __shared__ float a_s[16][68];
    __shared__ float b_s[16][68];
    int z = blockIdx.z;
    int bat = z / 3, which = z % 3;
    const float* A = (which == 0) ? wq : (which == 1) ? wk : wv;
    float* out = ((which == 0) ? g_q : (which == 1) ? g_k : g_v) + (size_t)bat * CC * SS;
    const float* Bm = g_norm + (size_t)bat * CC * SS;
    int t = threadIdx.x, tx = t & 15, ty = t >> 4;
    int m0 = blockIdx.y * 64, j0 = blockIdx.x * 64;
    float acc[4][4] = {};
    gemm_tile(A, Bm, acc, a_s, b_s, m0, j0, t, tx, ty);
    #pragma unroll
    for (int r = 0; r < 4; r++) {
        float4 v = make_float4(acc[r][0], acc[r][1], acc[r][2], acc[r][3]);
        *(float4*)&out[(size_t)(m0 + ty * 4 + r) * SS + j0 + tx * 4] = v;
    }
}

// ---------------- Output projection + bias + residual ----------------
__global__ void __launch_bounds__(256) proj_kernel(const float* __restrict__ wo,
                                                   const float* __restrict__ bo,
                                                   const float* __restrict__ x,
                                                   float* __restrict__ out) {
    __shared__ float a_s[16][68];
    __shared__ float b_s[16][68];
    int bat = blockIdx.z;
    const float* Bm = g_att + (size_t)bat * CC * SS;
    const float* xr = x + (size_t)bat * CC * SS;
    float* op = out + (size_t)bat * CC * SS;
    int t = threadIdx.x, tx = t & 15, ty = t >> 4;
    int m0 = blockIdx.y * 64, j0 = blockIdx.x * 64;
    float acc[4][4] = {};
    gemm_tile(wo, Bm, acc, a_s, b_s, m0, j0, t, tx, ty);
    #pragma unroll
    for (int r = 0; r < 4; r++) {
        int row = m0 + ty * 4 + r;
        float bv = bo[row];
        size_t off = (size_t)row * SS + j0 + tx * 4;
        float4 xv = *(const float4*)&xr[off];
        float4 v = make_float4(acc[r][0] + bv + xv.x, acc[r][1] + bv + xv.y,
                               acc[r][2] + bv + xv.z, acc[r][3] + bv + xv.w);
        *(float4*)&op[off] = v;
    }
}

// ---------------- Flash attention ----------------
// per block: one (batch, head, 64-query tile). smem: q[d][i], k[d][j], v[j][d], p[i][j]
__global__ void __launch_bounds__(256) flash_kernel() {
    extern __shared__ float sm[];
    float (*q_s)[68] = (float(*)[68])sm;
    float (*k_s)[68] = (float(*)[68])(sm + 64 * 68);
    float (*v_s)[68] = (float(*)[68])(sm + 2 * 64 * 68);
    float (*p_s)[68] = (float(*)[68])(sm + 3 * 64 * 68);

    int i0 = blockIdx.x * 64;
    int head = blockIdx.y, bat = blockIdx.z;
    size_t base = ((size_t)(bat * NHH + head)) * HDD * SS;
    const float* qp = g_q + base;
    const float* kp = g_k + base;
    const float* vp = g_v + base;
    float* op = g_att + base;

    int t = threadIdx.x, tx = t & 15, ty = t >> 4;

    // load Q tile, pre-scaled
    #pragma unroll
    for (int it = 0; it < 4; it++) {
        int idx = t + it * 256;
        int d = idx >> 4, i4 = idx & 15;
        float4 v = *(const float4*)&qp[(size_t)d * SS + i0 + i4 * 4];
        v.x *= SCALE; v.y *= SCALE; v.z *= SCALE; v.w *= SCALE;
        *(float4*)&q_s[d][i4 * 4] = v;
    }

    float m_r[4], l_r[4], o_r[4][4];
    #pragma unroll
    for (int r = 0; r < 4; r++) {
        m_r[r] = -1e30f; l_r[r] = 0.f;
        #pragma unroll
        for (int c = 0; c < 4; c++) o_r[r][c] = 0.f;
    }

    for (int jb = 0; jb < SS; jb += 64) {
        __syncthreads();  // prior PV reads of v_s/p_s done
        // load K tile [d][j], V tile transposed [j][d]
        #pragma unroll
        for (int it = 0; it < 4; it++) {
            int idx = t + it * 256;
            int d = idx >> 4, j4 = idx & 15;
            float4 kv = *(const float4*)&kp[(size_t)d * SS + jb + j4 * 4];
            *(float4*)&k_s[d][j4 * 4] = kv;
            float4 vv = *(const float4*)&vp[(size_t)d * SS + jb + j4 * 4];
            v_s[j4 * 4 + 0][d] = vv.x;
            v_s[j4 * 4 + 1][d] = vv.y;
            v_s[j4 * 4 + 2][d] = vv.z;
            v_s[j4 * 4 + 3][d] = vv.w;
        }
        __syncthreads();

        // S = Q^T K  (rows i = ty*4.., cols j = tx*4..)
        float s_r[4][4] = {};
        #pragma unroll 8
        for (int d = 0; d < 64; d++) {
            float4 a = *(float4*)&q_s[d][ty * 4];
            float4 bv = *(float4*)&k_s[d][tx * 4];
            s_r[0][0] += a.x * bv.x; s_r[0][1] += a.x * bv.y; s_r[0][2] += a.x * bv.z; s_r[0][3] += a.x * bv.w;
            s_r[1][0] += a.y * bv.x; s_r[1][1] += a.y * bv.y; s_r[1][2] += a.y * bv.z; s_r[1][3] += a.y * bv.w;
            s_r[2][0] += a.z * bv.x; s_r[2][1] += a.z * bv.y; s_r[2][2] += a.z * bv.z; s_r[2][3] += a.z * bv.w;
            s_r[3][0] += a.w * bv.x; s_r[3][1] += a.w * bv.y; s_r[3][2] += a.w * bv.z; s_r[3][3] += a.w * bv.w;
        }

        // online softmax; rows live in one 16-lane half-warp segment
        #pragma unroll
        for (int r = 0; r < 4; r++) {
            float rm = fmaxf(fmaxf(s_r[r][0], s_r[r][1]), fmaxf(s_r[r][2], s_r[r][3]));
            #pragma unroll
            for (int off = 8; off >= 1; off >>= 1)
                rm = fmaxf(rm, __shfl_xor_sync(0xffffffffu, rm, off, 16));
            float mn = fmaxf(m_r[r], rm);
            float corr = __expf(m_r[r] - mn);
            float rs = 0.f;
            #pragma unroll
            for (int c = 0; c < 4; c++) {
                s_r[r][c] = __expf(s_r[r][c] - mn);
                rs += s_r[r][c];
            }
            #pragma unroll
            for (int off = 8; off >= 1; off >>= 1)
                rs += __shfl_xor_sync(0xffffffffu, rs, off, 16);
            l_r[r] = l_r[r] * corr + rs;
            m_r[r] = mn;
            #pragma unroll
            for (int c = 0; c < 4; c++) o_r[r][c] *= corr;
            *(float4*)&p_s[ty * 4 + r][tx * 4] =
                make_float4(s_r[r][0], s_r[r][1], s_r[r][2], s_r[r][3]);
        }
        __syncthreads();

        // O += P * V   (o rows i = ty*4.., cols d = tx*4..)
        #pragma unroll 8
        for (int j = 0; j < 64; j++) {
            float4 vv = *(float4*)&v_s[j][tx * 4];
            float p0 = p_s[ty * 4 + 0][j];
            float p1 = p_s[ty * 4 + 1][j];
            float p2 = p_s[ty * 4 + 2][j];
            float p3 = p_s[ty * 4 + 3][j];
            o_r[0][0] += p0 * vv.x; o_r[0][1] += p0 * vv.y; o_r[0][2] += p0 * vv.z; o_r[0][3] += p0 * vv.w;
            o_r[1][0] += p1 * vv.x; o_r[1][1] += p1 * vv.y; o_r[1][2] += p1 * vv.z; o_r[1][3] += p1 * vv.w;
            o_r[2][0] += p2 * vv.x; o_r[2][1] += p2 * vv.y; o_r[2][2] += p2 * vv.z; o_r[2][3] += p2 * vv.w;
            o_r[3][0] += p3 * vv.x; o_r[3][1] += p3 * vv.y; o_r[3][2] += p3 * vv.z; o_r[3][3] += p3 * vv.w;
        }
    }

    // normalize, transpose through smem (reuse k_s as [d][i]), coalesced store
    __syncthreads();
    #pragma unroll
    for (int r = 0; r < 4; r++) {
        float inv_l = 1.0f / l_r[r];
        #pragma unroll
        for (int c = 0; c < 4; c++)
            k_s[tx * 4 + c][ty * 4 + r] = o_r[r][c] * inv_l;
    }
    __syncthreads();
    #pragma unroll
    for (int it = 0; it < 4; it++) {
        int idx = t + it * 256;
        int d = idx >> 4, i4 = idx & 15;
        *(float4*)&op[(size_t)d * SS + i0 + i4 * 4] = *(float4*)&k_s[d][i4 * 4];
    }
}

// ---------------- launch ----------------
extern "C" void kernel_launch(void* const* d_in, const int* in_sizes, int n_in,
                              void* d_out, int out_size) {
    const float* x    = (const float*)d_in[0];
    const float* gn_w = (const float*)d_in[1];
    const float* gn_b = (const float*)d_in[2];
    const float* wq   = (const float*)d_in[3];
    const float* wk   = (const float*)d_in[4];
    const float* wv   = (const float*)d_in[5];
    const float* wo   = (const float*)d_in[6];
    const float* bo   = (const float*)d_in[7];
    float* out = (float*)d_out;

    static int smem_set = 0;
    if (!smem_set) {
        cudaFuncSetAttribute(flash_kernel, cudaFuncAttributeMaxDynamicSharedMemorySize,
                             4 * 64 * 68 * (int)sizeof(float));
        smem_set = 1;
    }

    // 1) GroupNorm
    gn_kernel<<<BB * NGROUPS, 256>>>(x, gn_w, gn_b);
    // 2) Q/K/V projections
    {
        dim3 grid(SS / 64, CC / 64, BB * 3);
        qkv_kernel<<<grid, 256>>>(wq, wk, wv);
    }
    // 3) flash attention
    {
        dim3 grid(SS / 64, NHH, BB);
        flash_kernel<<<grid, 256, 4 * 64 * 68 * (int)sizeof(float)>>>();
    }
    // 4) output projection + bias + residual
    {
        dim3 grid(SS / 64, CC / 64, BB);
        proj_kernel<<<grid, 256>>>(wo, bo, x, out);
    }
}

// round 2
// speedup vs baseline: 2.7883x; 2.7883x over previous
#include <cuda_runtime.h>
#include <cuda_bf16.h>

#define SS 4096
#define CC 256
#define BB 2
#define NHH 4
#define HDD 64
#define NGROUPS 32
#define CPG 8
#define SCALE 0.0625f  // 1/sqrt(256)

// scratch (allocation-free rule: __device__ globals)
__device__ float g_norm[BB*CC*SS];
__device__ float g_q[BB*CC*SS];
__device__ float g_k[BB*CC*SS];
__device__ float g_v[BB*CC*SS];
__device__ float g_att[BB*CC*SS];

// ---------------- helpers ----------------
__device__ __forceinline__ float to_tf32(float x) {
    unsigned r;
    asm("cvt.rna.tf32.f32 %0, %1;" : "=r"(r) : "f"(x));
    return __uint_as_float(r);
}

__device__ __forceinline__ void mma_tf32(float c[4], const float a[4], float b0, float b1) {
    asm volatile(
        "mma.sync.aligned.m16n8k8.row.col.f32.tf32.tf32.f32 "
        "{%0,%1,%2,%3}, {%4,%5,%6,%7}, {%8,%9}, {%0,%1,%2,%3};"
        : "+f"(c[0]), "+f"(c[1]), "+f"(c[2]), "+f"(c[3])
        : "r"(__float_as_uint(a[0])), "r"(__float_as_uint(a[1])),
          "r"(__float_as_uint(a[2])), "r"(__float_as_uint(a[3])),
          "r"(__float_as_uint(b0)), "r"(__float_as_uint(b1)));
}

// ---------------- GroupNorm ----------------
__global__ void __launch_bounds__(256) gn_kernel(const float* __restrict__ x,
                                                 const float* __restrict__ w,
                                                 const float* __restrict__ b) {
    int grp = blockIdx.x;                       // b*32 + g
    const float* xp = x + (size_t)grp * CPG * SS;
    float* op = g_norm + (size_t)grp * CPG * SS;
    int t = threadIdx.x;
    const int n4 = CPG * SS / 4;                // 8192 float4s
    const float4* x4 = (const float4*)xp;
    float s0 = 0.f, s1 = 0.f;
    for (int i = t; i < n4; i += 256) {
        float4 v = x4[i];
        s0 += v.x + v.y + v.z + v.w;
        s1 += v.x*v.x + v.y*v.y + v.z*v.z + v.w*v.w;
    }
    __shared__ float r0[256], r1[256];
    r0[t] = s0; r1[t] = s1; __syncthreads();
    for (int o = 128; o > 0; o >>= 1) {
        if (t < o) { r0[t] += r0[t+o]; r1[t] += r1[t+o]; }
        __syncthreads();
    }
    __shared__ float mu_s, rs_s;
    if (t == 0) {
        float inv_n = 1.0f / (CPG * SS);
        float mu = r0[0] * inv_n;
        float var = r1[0] * inv_n - mu * mu;
        mu_s = mu;
        rs_s = rsqrtf(var + 1e-5f);
    }
    __syncthreads();
    float mu = mu_s, rs = rs_s;
    int g = grp % NGROUPS;
    float4* o4 = (float4*)op;
    for (int i = t; i < n4; i += 256) {
        int c = g * CPG + (i * 4) / SS;        // 4 elems share channel (SS%4==0)
        float wc = w[c], bc = b[c];
        float4 v = x4[i];
        v.x = (v.x - mu) * rs * wc + bc;
        v.y = (v.y - mu) * rs * wc + bc;
        v.z = (v.z - mu) * rs * wc + bc;
        v.w = (v.w - mu) * rs * wc + bc;
        o4[i] = v;
    }
}

// ---------------- Tiled SGEMM body (64x64 tile, 4x4 micro, BK=16) ----------------
__device__ __forceinline__ void gemm_tile(const float* __restrict__ A,
                                          const float* __restrict__ Bm,
                                          float acc[4][4],
                                          float (*a_s)[68], float (*b_s)[68],
                                          int m0, int j0, int t, int tx, int ty) {
    for (int k0 = 0; k0 < CC; k0 += 16) {
        {
            int m = t >> 2, kq = (t & 3) * 4;
            float4 av = *(const float4*)&A[(size_t)(m0 + m) * CC + k0 + kq];
            a_s[kq+0][m] = av.x; a_s[kq+1][m] = av.y;
            a_s[kq+2][m] = av.z; a_s[kq+3][m] = av.w;
            int kk = t >> 4, j4 = t & 15;
            float4 bv = *(const float4*)&Bm[(size_t)(k0 + kk) * SS + j0 + j4 * 4];
            *(float4*)&b_s[kk][j4 * 4] = bv;
        }
        __syncthreads();
        #pragma unroll
        for (int kk = 0; kk < 16; kk++) {
            float4 a = *(float4*)&a_s[kk][ty * 4];
            float4 bv = *(float4*)&b_s[kk][tx * 4];
            acc[0][0] += a.x * bv.x; acc[0][1] += a.x * bv.y; acc[0][2] += a.x * bv.z; acc[0][3] += a.x * bv.w;
            acc[1][0] += a.y * bv.x; acc[1][1] += a.y * bv.y; acc[1][2] += a.y * bv.z; acc[1][3] += a.y * bv.w;
            acc[2][0] += a.z * bv.x; acc[2][1] += a.z * bv.y; acc[2][2] += a.z * bv.z; acc[2][3] += a.z * bv.w;
            acc[3][0] += a.w * bv.x; acc[3][1] += a.w * bv.y; acc[3][2] += a.w * bv.z; acc[3][3] += a.w * bv.w;
        }
        __syncthreads();
    }
}

// ---------------- QKV projection ----------------
__global__ void __launch_bounds__(256) qkv_kernel(const float* __restrict__ wq,
                                                  const float* __restrict__ wk,
                                                  const float* __restrict__ wv) {
    __shared__ float a_s[16][68];
    __shared__ float b_s[16][68];
    int z = blockIdx.z;
    int bat = z / 3, which = z % 3;
    const float* A = (which == 0) ? wq : (which == 1) ? wk : wv;
    float* out = ((which == 0) ? g_q : (which == 1) ? g_k : g_v) + (size_t)bat * CC * SS;
    const float* Bm = g_norm + (size_t)bat * CC * SS;
    int t = threadIdx.x, tx = t & 15, ty = t >> 4;
    int m0 = blockIdx.y * 64, j0 = blockIdx.x * 64;
    float acc[4][4] = {};
    gemm_tile(A, Bm, acc, a_s, b_s, m0, j0, t, tx, ty);
    #pragma unroll
    for (int r = 0; r < 4; r++) {
        float4 v = make_float4(acc[r][0], acc[r][1], acc[r][2], acc[r][3]);
        *(float4*)&out[(size_t)(m0 + ty * 4 + r) * SS + j0 + tx * 4] = v;
    }
}

// ---------------- Output projection + bias + residual ----------------
__global__ void __launch_bounds__(256) proj_kernel(const float* __restrict__ wo,
                                                   const float* __restrict__ bo,
                                                   const float* __restrict__ x,
                                                   float* __restrict__ out) {
    __shared__ float a_s[16][68];
    __shared__ float b_s[16][68];
    int bat = blockIdx.z;
    const float* Bm = g_att + (size_t)bat * CC * SS;
    const float* xr = x + (size_t)bat * CC * SS;
    float* op = out + (size_t)bat * CC * SS;
    int t = threadIdx.x, tx = t & 15, ty = t >> 4;
    int m0 = blockIdx.y * 64, j0 = blockIdx.x * 64;
    float acc[4][4] = {};
    gemm_tile(wo, Bm, acc, a_s, b_s, m0, j0, t, tx, ty);
    #pragma unroll
    for (int r = 0; r < 4; r++) {
        int row = m0 + ty * 4 + r;
        float bv = bo[row];
        size_t off = (size_t)row * SS + j0 + tx * 4;
        float4 xv = *(const float4*)&xr[off];
        float4 v = make_float4(acc[r][0] + bv + xv.x, acc[r][1] + bv + xv.y,
                               acc[r][2] + bv + xv.z, acc[r][3] + bv + xv.w);
        *(float4*)&op[off] = v;
    }
}

// ---------------- Flash attention with tf32 mma ----------------
// Block: (batch, head, 128-query tile). 8 warps; each warp owns 16 query rows.
// smem: q_s[64][132] as [d][i]; k_s[64][72] as [d][key]; v_s[64][68] as [d][key];
//       p_s[128][68] as [row][key] (reused as O staging [d][i] stride 132 at the end)
#define KPAD 72
#define VPAD 68
#define PPAD 68
#define QSTRIDE 132

#define SM_Q 0
#define SM_K (64*QSTRIDE)
#define SM_V (SM_K + 64*KPAD)
#define SM_P (SM_V + 64*VPAD)
#define SM_TOTAL_F (SM_P + 128*PPAD)   // floats

__global__ void __launch_bounds__(256, 2) flash_mma_kernel() {
    extern __shared__ float sm[];
    float* q_s = sm + SM_Q;
    float* k_s = sm + SM_K;
    float* v_s = sm + SM_V;
    float* p_s = sm + SM_P;

    int i0 = blockIdx.x * 128;
    int head = blockIdx.y, bat = blockIdx.z;
    size_t base = ((size_t)(bat * NHH + head)) * HDD * SS;
    const float* qp = g_q + base;
    const float* kp = g_k + base;
    const float* vp = g_v + base;
    float* op = g_att + base;

    int t = threadIdx.x;
    int lane = t & 31;
    int qr = lane >> 2, qc = lane & 3;   // quad row (0-7) / quad col (0-3)
    int w16 = (t >> 5) * 16;             // warp's row base

    // stage Q [d][i], pre-scaled, tf32-rounded
    #pragma unroll
    for (int it = 0; it < 8; it++) {
        int idx = t + it * 256;
        int d = idx >> 5, i8 = idx & 31;
        float4 v = *(const float4*)&qp[(size_t)d * SS + i0 + i8 * 4];
        v.x = to_tf32(v.x * SCALE); v.y = to_tf32(v.y * SCALE);
        v.z = to_tf32(v.z * SCALE); v.w = to_tf32(v.w * SCALE);
        *(float4*)&q_s[d * QSTRIDE + i8 * 4] = v;
    }
    __syncthreads();

    float mA = -1e30f, mB = -1e30f, lA = 0.f, lB = 0.f;
    float o[8][4];
    #pragma unroll
    for (int nt = 0; nt < 8; nt++) {
        o[nt][0] = 0.f; o[nt][1] = 0.f; o[nt][2] = 0.f; o[nt][3] = 0.f;
    }

    for (int jb = 0; jb < SS; jb += 64) {
        __syncthreads();
        // load K,V tiles [d][key], tf32-rounded
        #pragma unroll
        for (int it = 0; it < 4; it++) {
            int idx = t + it * 256;
            int d = idx >> 4, j4 = idx & 15;
            float4 kv = *(const float4*)&kp[(size_t)d * SS + jb + j4 * 4];
            kv.x = to_tf32(kv.x); kv.y = to_tf32(kv.y);
            kv.z = to_tf32(kv.z); kv.w = to_tf32(kv.w);
            *(float4*)&k_s[d * KPAD + j4 * 4] = kv;
            float4 vv = *(const float4*)&vp[(size_t)d * SS + jb + j4 * 4];
            vv.x = to_tf32(vv.x); vv.y = to_tf32(vv.y);
            vv.z = to_tf32(vv.z); vv.w = to_tf32(vv.w);
            *(float4*)&v_s[d * VPAD + j4 * 4] = vv;
        }
        __syncthreads();

        // S = Q K^T : warp's 16 rows x 64 keys = 8 n-tiles, 8 k-steps over d
        float s[8][4];
        #pragma unroll
        for (int nt = 0; nt < 8; nt++) {
            s[nt][0] = 0.f; s[nt][1] = 0.f; s[nt][2] = 0.f; s[nt][3] = 0.f;
        }
        #pragma unroll
        for (int kd = 0; kd < 8; kd++) {
            int dcol = kd * 8 + qc;
            float a[4];
            a[0] = q_s[dcol * QSTRIDE + w16 + qr];
            a[1] = q_s[dcol * QSTRIDE + w16 + qr + 8];
            a[2] = q_s[(dcol + 4) * QSTRIDE + w16 + qr];
            a[3] = q_s[(dcol + 4) * QSTRIDE + w16 + qr + 8];
            int r0 = dcol * KPAD;
            int r1 = r0 + 4 * KPAD;
            #pragma unroll
            for (int nt = 0; nt < 8; nt++) {
                float b0 = k_s[r0 + nt * 8 + qr];
                float b1 = k_s[r1 + nt * 8 + qr];
                mma_tf32(s[nt], a, b0, b1);
            }
        }

        // online softmax; lane owns 2 rows: A=w16+qr (c0,c1), B=w16+qr+8 (c2,c3)
        float mxA = s[0][0], mxB = s[0][2];
        #pragma unroll
        for (int nt = 0; nt < 8; nt++) {
            mxA = fmaxf(mxA, fmaxf(s[nt][0], s[nt][1]));
            mxB = fmaxf(mxB, fmaxf(s[nt][2], s[nt][3]));
        }
        mxA = fmaxf(mxA, __shfl_xor_sync(0xffffffffu, mxA, 1));
        mxA = fmaxf(mxA, __shfl_xor_sync(0xffffffffu, mxA, 2));
        mxB = fmaxf(mxB, __shfl_xor_sync(0xffffffffu, mxB, 1));
        mxB = fmaxf(mxB, __shfl_xor_sync(0xffffffffu, mxB, 2));
        float mAn = fmaxf(mA, mxA), mBn = fmaxf(mB, mxB);
        float cA = __expf(mA - mAn), cB = __expf(mB - mBn);
        float sA = 0.f, sB = 0.f;
        #pragma unroll
        for (int nt = 0; nt < 8; nt++) {
            s[nt][0] = __expf(s[nt][0] - mAn); sA += s[nt][0];
            s[nt][1] = __expf(s[nt][1] - mAn); sA += s[nt][1];
            s[nt][2] = __expf(s[nt][2] - mBn); sB += s[nt][2];
            s[nt][3] = __expf(s[nt][3] - mBn); sB += s[nt][3];
        }
        sA += __shfl_xor_sync(0xffffffffu, sA, 1);
        sA += __shfl_xor_sync(0xffffffffu, sA, 2);
        sB += __shfl_xor_sync(0xffffffffu, sB, 1);
        sB += __shfl_xor_sync(0xffffffffu, sB, 2);
        lA = lA * cA + sA; lB = lB * cB + sB;
        mA = mAn; mB = mBn;
        #pragma unroll
        for (int nt = 0; nt < 8; nt++) {
            o[nt][0] *= cA; o[nt][1] *= cA;
            o[nt][2] *= cB; o[nt][3] *= cB;
        }

        // write P to p_s[row][key] (each warp touches only its own 16 rows)
        #pragma unroll
        for (int nt = 0; nt < 8; nt++) {
            *(float2*)&p_s[(w16 + qr) * PPAD + nt * 8 + 2 * qc] = make_float2(s[nt][0], s[nt][1]);
            *(float2*)&p_s[(w16 + qr + 8) * PPAD + nt * 8 + 2 * qc] = make_float2(s[nt][2], s[nt][3]);
        }
        __syncwarp();

        // O += P V : 8 n-tiles over d, 8 k-steps over keys
        #pragma unroll
        for (int kj = 0; kj < 8; kj++) {
            float pa[4];
            pa[0] = p_s[(w16 + qr) * PPAD + kj * 8 + qc];
            pa[1] = p_s[(w16 + qr + 8) * PPAD + kj * 8 + qc];
            pa[2] = p_s[(w16 + qr) * PPAD + kj * 8 + qc + 4];
            pa[3] = p_s[(w16 + qr + 8) * PPAD + kj * 8 + qc + 4];
            #pragma unroll
            for (int nt = 0; nt < 8; nt++) {
                float b0 = v_s[(nt * 8 + qr) * VPAD + kj * 8 + qc];
                float b1 = v_s[(nt * 8 + qr) * VPAD + kj * 8 + qc + 4];
                mma_tf32(o[nt], pa, b0, b1);
            }
        }
    }

    // normalize, stage O as [d][i] (stride QSTRIDE) in p_s, then coalesced store
    __syncthreads();
    float rA = 1.f / lA, rB = 1.f / lB;
    #pragma unroll
    for (int nt = 0; nt < 8; nt++) {
        p_s[(nt * 8 + 2 * qc) * QSTRIDE + w16 + qr]         = o[nt][0] * rA;
        p_s[(nt * 8 + 2 * qc + 1) * QSTRIDE + w16 + qr]     = o[nt][1] * rA;
        p_s[(nt * 8 + 2 * qc) * QSTRIDE + w16 + qr + 8]     = o[nt][2] * rB;
        p_s[(nt * 8 + 2 * qc + 1) * QSTRIDE + w16 + qr + 8] = o[nt][3] * rB;
    }
    __syncthreads();
    #pragma unroll
    for (int it = 0; it < 8; it++) {
        int idx = t + it * 256;
        int d = idx >> 5, i8 = idx & 31;
        *(float4*)&op[(size_t)d * SS + i0 + i8 * 4] = *(float4*)&p_s[d * QSTRIDE + i8 * 4];
    }
}

// ---------------- launch ----------------
extern "C" void kernel_launch(void* const* d_in, const int* in_sizes, int n_in,
                              void* d_out, int out_size) {
    const float* x    = (const float*)d_in[0];
    const float* gn_w = (const float*)d_in[1];
    const float* gn_b = (const float*)d_in[2];
    const float* wq   = (const float*)d_in[3];
    const float* wk   = (const float*)d_in[4];
    const float* wv   = (const float*)d_in[5];
    const float* wo   = (const float*)d_in[6];
    const float* bo   = (const float*)d_in[7];
    float* out = (float*)d_out;

    static int smem_set = 0;
    if (!smem_set) {
        cudaFuncSetAttribute(flash_mma_kernel, cudaFuncAttributeMaxDynamicSharedMemorySize,
                             SM_TOTAL_F * (int)sizeof(float));
        smem_set = 1;
    }

    // 1) GroupNorm
    gn_kernel<<<BB * NGROUPS, 256>>>(x, gn_w, gn_b);
    // 2) Q/K/V projections
    {
        dim3 grid(SS / 64, CC / 64, BB * 3);
        qkv_kernel<<<grid, 256>>>(wq, wk, wv);
    }
    // 3) flash attention (tf32 tensor core)
    {
        dim3 grid(SS / 128, NHH, BB);
        flash_mma_kernel<<<grid, 256, SM_TOTAL_F * (int)sizeof(float)>>>();
    }
    // 4) output projection + bias + residual
    {
        dim3 grid(SS / 64, CC / 64, BB);
        proj_kernel<<<grid, 256>>>(wo, bo, x, out);
    }
}

// round 3
// speedup vs baseline: 3.3138x; 1.1885x over previous
#include <cuda_runtime.h>
#include <cuda_bf16.h>

#define SS 4096
#define CC 256
#define BB 2
#define NHH 4
#define HDD 64
#define NGROUPS 32
#define CPG 8
#define SCALE 0.0625f  // 1/sqrt(256)

// scratch (allocation-free rule: __device__ globals)
__device__ float g_norm[BB*CC*SS];
__device__ float g_q[BB*CC*SS];
__device__ float g_k[BB*CC*SS];
__device__ float g_v[BB*CC*SS];
__device__ float g_att[BB*CC*SS];

// ---------------- helpers ----------------
__device__ __forceinline__ float to_tf32(float x) {
    unsigned r;
    asm("cvt.rna.tf32.f32 %0, %1;" : "=r"(r) : "f"(x));
    return __uint_as_float(r);
}

__device__ __forceinline__ void mma_tf32(float c[4], const float a[4], float b0, float b1) {
    asm volatile(
        "mma.sync.aligned.m16n8k8.row.col.f32.tf32.tf32.f32 "
        "{%0,%1,%2,%3}, {%4,%5,%6,%7}, {%8,%9}, {%0,%1,%2,%3};"
        : "+f"(c[0]), "+f"(c[1]), "+f"(c[2]), "+f"(c[3])
        : "r"(__float_as_uint(a[0])), "r"(__float_as_uint(a[1])),
          "r"(__float_as_uint(a[2])), "r"(__float_as_uint(a[3])),
          "r"(__float_as_uint(b0)), "r"(__float_as_uint(b1)));
}

// ---------------- GroupNorm ----------------
__global__ void __launch_bounds__(256) gn_kernel(const float* __restrict__ x,
                                                 const float* __restrict__ w,
                                                 const float* __restrict__ b) {
    int grp = blockIdx.x;                       // b*32 + g
    const float* xp = x + (size_t)grp * CPG * SS;
    float* op = g_norm + (size_t)grp * CPG * SS;
    int t = threadIdx.x;
    const int n4 = CPG * SS / 4;                // 8192 float4s
    const float4* x4 = (const float4*)xp;
    float s0 = 0.f, s1 = 0.f;
    for (int i = t; i < n4; i += 256) {
        float4 v = x4[i];
        s0 += v.x + v.y + v.z + v.w;
        s1 += v.x*v.x + v.y*v.y + v.z*v.z + v.w*v.w;
    }
    __shared__ float r0[256], r1[256];
    r0[t] = s0; r1[t] = s1; __syncthreads();
    for (int o = 128; o > 0; o >>= 1) {
        if (t < o) { r0[t] += r0[t+o]; r1[t] += r1[t+o]; }
        __syncthreads();
    }
    __shared__ float mu_s, rs_s;
    if (t == 0) {
        float inv_n = 1.0f / (CPG * SS);
        float mu = r0[0] * inv_n;
        float var = r1[0] * inv_n - mu * mu;
        mu_s = mu;
        rs_s = rsqrtf(var + 1e-5f);
    }
    __syncthreads();
    float mu = mu_s, rs = rs_s;
    int g = grp % NGROUPS;
    float4* o4 = (float4*)op;
    for (int i = t; i < n4; i += 256) {
        int c = g * CPG + (i * 4) / SS;        // 4 elems share channel (SS%4==0)
        float wc = w[c], bc = b[c];
        float4 v = x4[i];
        v.x = (v.x - mu) * rs * wc + bc;
        v.y = (v.y - mu) * rs * wc + bc;
        v.z = (v.z - mu) * rs * wc + bc;
        v.w = (v.w - mu) * rs * wc + bc;
        o4[i] = v;
    }
}

// ---------------- tf32 MMA GEMM: C[256][4096] = A[256][256] * X[256][4096] --------
// CTA tile 128x128, 8 warps (2m x 4n), warp tile 64x32, BK=16, double buffered.
#define GST 136   // smem row stride (mod 32 == 8 -> conflict-free fragment LDS)

struct MMLoad {
    float4 a0, a1, x0, x1;
};

__device__ __forceinline__ void mm_ldg(MMLoad& L, const float* __restrict__ A,
                                       const float* __restrict__ X,
                                       int m0, int n0, int kb, int t) {
    int m = t >> 1, kk = (t & 1) * 8;
    const float* ap = &A[(size_t)(m0 + m) * CC + kb * 16 + kk];
    L.a0 = *(const float4*)ap;
    L.a1 = *(const float4*)(ap + 4);
    int k = t >> 5, n = (t & 31) * 4;
    L.x0 = *(const float4*)&X[(size_t)(kb * 16 + k) * SS + n0 + n];
    L.x1 = *(const float4*)&X[(size_t)(kb * 16 + k + 8) * SS + n0 + n];
}

__device__ __forceinline__ void mm_sts(const MMLoad& L, float* a_s, float* x_s, int t) {
    int m = t >> 1, kk = (t & 1) * 8;
    a_s[(kk + 0) * GST + m] = to_tf32(L.a0.x);
    a_s[(kk + 1) * GST + m] = to_tf32(L.a0.y);
    a_s[(kk + 2) * GST + m] = to_tf32(L.a0.z);
    a_s[(kk + 3) * GST + m] = to_tf32(L.a0.w);
    a_s[(kk + 4) * GST + m] = to_tf32(L.a1.x);
    a_s[(kk + 5) * GST + m] = to_tf32(L.a1.y);
    a_s[(kk + 6) * GST + m] = to_tf32(L.a1.z);
    a_s[(kk + 7) * GST + m] = to_tf32(L.a1.w);
    int k = t >> 5, n = (t & 31) * 4;
    float4 v0 = make_float4(to_tf32(L.x0.x), to_tf32(L.x0.y), to_tf32(L.x0.z), to_tf32(L.x0.w));
    float4 v1 = make_float4(to_tf32(L.x1.x), to_tf32(L.x1.y), to_tf32(L.x1.z), to_tf32(L.x1.w));
    *(float4*)&x_s[k * GST + n] = v0;
    *(float4*)&x_s[(k + 8) * GST + n] = v1;
}

__device__ __forceinline__ void mm_compute(const float* a_s, const float* x_s,
                                           float acc[4][4][4], int wm, int wn,
                                           int qr, int qc) {
    #pragma unroll
    for (int k8 = 0; k8 < 2; k8++) {
        float a[4][4];
        #pragma unroll
        for (int mt = 0; mt < 4; mt++) {
            int mb = wm * 64 + mt * 16;
            a[mt][0] = a_s[(k8 * 8 + qc) * GST + mb + qr];
            a[mt][1] = a_s[(k8 * 8 + qc) * GST + mb + qr + 8];
            a[mt][2] = a_s[(k8 * 8 + qc + 4) * GST + mb + qr];
            a[mt][3] = a_s[(k8 * 8 + qc + 4) * GST + mb + qr + 8];
        }
        #pragma unroll
        for (int nt = 0; nt < 4; nt++) {
            int nb = wn * 32 + nt * 8;
            float b0 = x_s[(k8 * 8 + qc) * GST + nb + qr];
            float b1 = x_s[(k8 * 8 + qc + 4) * GST + nb + qr];
            #pragma unroll
            for (int mt = 0; mt < 4; mt++)
                mma_tf32(acc[mt][nt], a[mt], b0, b1);
        }
    }
}

// core loop producing acc for one (m0, n0) tile
__device__ __forceinline__ void mm_main(const float* __restrict__ A,
                                        const float* __restrict__ X,
                                        float acc[4][4][4],
                                        float* a_sm, float* x_sm,
                                        int m0, int n0, int t, int wm, int wn,
                                        int qr, int qc) {
    MMLoad L;
    mm_ldg(L, A, X, m0, n0, 0, t);
    mm_sts(L, a_sm, x_sm, t);
    __syncthreads();
    for (int kb = 0; kb < 16; kb++) {
        int cur = kb & 1;
        if (kb < 15) mm_ldg(L, A, X, m0, n0, kb + 1, t);
        mm_compute(a_sm + cur * (16 * GST), x_sm + cur * (16 * GST), acc, wm, wn, qr, qc);
        if (kb < 15) mm_sts(L, a_sm + (cur ^ 1) * (16 * GST), x_sm + (cur ^ 1) * (16 * GST), t);
        __syncthreads();
    }
}

// QKV: z = bat*3 + which; writes tf32-rounded outputs (consumed by flash as tf32)
__global__ void __launch_bounds__(256) qkv_mm_kernel(const float* __restrict__ wq,
                                                     const float* __restrict__ wk,
                                                     const float* __restrict__ wv) {
    __shared__ float a_sm[2 * 16 * GST];
    __shared__ float x_sm[2 * 16 * GST];
    int z = blockIdx.z;
    int bat = z / 3, which = z % 3;
    const float* A = (which == 0) ? wq : (which == 1) ? wk : wv;
    float* out = ((which == 0) ? g_q : (which == 1) ? g_k : g_v) + (size_t)bat * CC * SS;
    const float* X = g_norm + (size_t)bat * CC * SS;

    int t = threadIdx.x, lane = t & 31;
    int qr = lane >> 2, qc = lane & 3;
    int wid = t >> 5, wm = wid >> 2, wn = wid & 3;
    int m0 = blockIdx.y * 128, n0 = blockIdx.x * 128;

    float acc[4][4][4] = {};
    mm_main(A, X, acc, a_sm, x_sm, m0, n0, t, wm, wn, qr, qc);

    #pragma unroll
    for (int mt = 0; mt < 4; mt++) {
        int row = m0 + wm * 64 + mt * 16 + qr;
        #pragma unroll
        for (int nt = 0; nt < 4; nt++) {
            int col = n0 + wn * 32 + nt * 8 + 2 * qc;
            *(float2*)&out[(size_t)row * SS + col] =
                make_float2(to_tf32(acc[mt][nt][0]), to_tf32(acc[mt][nt][1]));
            *(float2*)&out[(size_t)(row + 8) * SS + col] =
                make_float2(to_tf32(acc[mt][nt][2]), to_tf32(acc[mt][nt][3]));
        }
    }
}

// proj: out = wo * g_att + bo + x   (full fp32 output)
__global__ void __launch_bounds__(256) proj_mm_kernel(const float* __restrict__ wo,
                                                      const float* __restrict__ bo,
                                                      const float* __restrict__ x,
                                                      float* __restrict__ out) {
    __shared__ float a_sm[2 * 16 * GST];
    __shared__ float x_sm[2 * 16 * GST];
    int bat = blockIdx.z;
    const float* X = g_att + (size_t)bat * CC * SS;
    const float* xr = x + (size_t)bat * CC * SS;
    float* op = out + (size_t)bat * CC * SS;

    int t = threadIdx.x, lane = t & 31;
    int qr = lane >> 2, qc = lane & 3;
    int wid = t >> 5, wm = wid >> 2, wn = wid & 3;
    int m0 = blockIdx.y * 128, n0 = blockIdx.x * 128;

    float acc[4][4][4] = {};
    mm_main(wo, X, acc, a_sm, x_sm, m0, n0, t, wm, wn, qr, qc);

    #pragma unroll
    for (int mt = 0; mt < 4; mt++) {
        int row = m0 + wm * 64 + mt * 16 + qr;
        float bv0 = bo[row], bv1 = bo[row + 8];
        #pragma unroll
        for (int nt = 0; nt < 4; nt++) {
            int col = n0 + wn * 32 + nt * 8 + 2 * qc;
            size_t off0 = (size_t)row * SS + col;
            size_t off1 = (size_t)(row + 8) * SS + col;
            float2 r0 = *(const float2*)&xr[off0];
            float2 r1 = *(const float2*)&xr[off1];
            *(float2*)&op[off0] = make_float2(acc[mt][nt][0] + bv0 + r0.x,
                                              acc[mt][nt][1] + bv0 + r0.y);
            *(float2*)&op[off1] = make_float2(acc[mt][nt][2] + bv1 + r1.x,
                                              acc[mt][nt][3] + bv1 + r1.y);
        }
    }
}

// ---------------- Flash attention with tf32 mma ----------------
// Q/K/V arrive already tf32-rounded from qkv_mm_kernel.
#define KPAD 72
#define VPAD 68
#define PPAD 68
#define QSTRIDE 132

#define SM_Q 0
#define SM_K (64*QSTRIDE)
#define SM_V (SM_K + 64*KPAD)
#define SM_P (SM_V + 64*VPAD)
#define SM_TOTAL_F (SM_P + 128*PPAD)   // floats

__global__ void __launch_bounds__(256, 2) flash_mma_kernel() {
    extern __shared__ float sm[];
    float* q_s = sm + SM_Q;
    float* k_s = sm + SM_K;
    float* v_s = sm + SM_V;
    float* p_s = sm + SM_P;

    int i0 = blockIdx.x * 128;
    int head = blockIdx.y, bat = blockIdx.z;
    size_t base = ((size_t)(bat * NHH + head)) * HDD * SS;
    const float* qp = g_q + base;
    const float* kp = g_k + base;
    const float* vp = g_v + base;
    float* op = g_att + base;

    int t = threadIdx.x;
    int lane = t & 31;
    int qr = lane >> 2, qc = lane & 3;   // quad row (0-7) / quad col (0-3)
    int w16 = (t >> 5) * 16;             // warp's row base

    // stage Q [d][i]; values are tf32 already, scale by 2^-4 (exact)
    #pragma unroll
    for (int it = 0; it < 8; it++) {
        int idx = t + it * 256;
        int d = idx >> 5, i8 = idx & 31;
        float4 v = *(const float4*)&qp[(size_t)d * SS + i0 + i8 * 4];
        v.x *= SCALE; v.y *= SCALE; v.z *= SCALE; v.w *= SCALE;
        *(float4*)&q_s[d * QSTRIDE + i8 * 4] = v;
    }
    __syncthreads();

    float mA = -1e30f, mB = -1e30f, lA = 0.f, lB = 0.f;
    float o[8][4];
    #pragma unroll
    for (int nt = 0; nt < 8; nt++) {
        o[nt][0] = 0.f; o[nt][1] = 0.f; o[nt][2] = 0.f; o[nt][3] = 0.f;
    }

    for (int jb = 0; jb < SS; jb += 64) {
        __syncthreads();
        // load K,V tiles [d][key] (already tf32)
        #pragma unroll
        for (int it = 0; it < 4; it++) {
            int idx = t + it * 256;
            int d = idx >> 4, j4 = idx & 15;
            float4 kv = *(const float4*)&kp[(size_t)d * SS + jb + j4 * 4];
            *(float4*)&k_s[d * KPAD + j4 * 4] = kv;
            float4 vv = *(const float4*)&vp[(size_t)d * SS + jb + j4 * 4];
            *(float4*)&v_s[d * VPAD + j4 * 4] = vv;
        }
        __syncthreads();

        // S = Q K^T
        float s[8][4];
        #pragma unroll
        for (int nt = 0; nt < 8; nt++) {
            s[nt][0] = 0.f; s[nt][1] = 0.f; s[nt][2] = 0.f; s[nt][3] = 0.f;
        }
        #pragma unroll
        for (int kd = 0; kd < 8; kd++) {
            int dcol = kd * 8 + qc;
            float a[4];
            a[0] = q_s[dcol * QSTRIDE + w16 + qr];
            a[1] = q_s[dcol * QSTRIDE + w16 + qr + 8];
            a[2] = q_s[(dcol + 4) * QSTRIDE + w16 + qr];
            a[3] = q_s[(dcol + 4) * QSTRIDE + w16 + qr + 8];
            int r0 = dcol * KPAD;
            int r1 = r0 + 4 * KPAD;
            #pragma unroll
            for (int nt = 0; nt < 8; nt++) {
                float b0 = k_s[r0 + nt * 8 + qr];
                float b1 = k_s[r1 + nt * 8 + qr];
                mma_tf32(s[nt], a, b0, b1);
            }
        }

        // online softmax; lane owns 2 rows
        float mxA = s[0][0], mxB = s[0][2];
        #pragma unroll
        for (int nt = 0; nt < 8; nt++) {
            mxA = fmaxf(mxA, fmaxf(s[nt][0], s[nt][1]));
            mxB = fmaxf(mxB, fmaxf(s[nt][2], s[nt][3]));
        }
        mxA = fmaxf(mxA, __shfl_xor_sync(0xffffffffu, mxA, 1));
        mxA = fmaxf(mxA, __shfl_xor_sync(0xffffffffu, mxA, 2));
        mxB = fmaxf(mxB, __shfl_xor_sync(0xffffffffu, mxB, 1));
        mxB = fmaxf(mxB, __shfl_xor_sync(0xffffffffu, mxB, 2));
        float mAn = fmaxf(mA, mxA), mBn = fmaxf(mB, mxB);
        float cA = __expf(mA - mAn), cB = __expf(mB - mBn);
        float sA = 0.f, sB = 0.f;
        #pragma unroll
        for (int nt = 0; nt < 8; nt++) {
            s[nt][0] = __expf(s[nt][0] - mAn); sA += s[nt][0];
            s[nt][1] = __expf(s[nt][1] - mAn); sA += s[nt][1];
            s[nt][2] = __expf(s[nt][2] - mBn); sB += s[nt][2];
            s[nt][3] = __expf(s[nt][3] - mBn); sB += s[nt][3];
        }
        sA += __shfl_xor_sync(0xffffffffu, sA, 1);
        sA += __shfl_xor_sync(0xffffffffu, sA, 2);
        sB += __shfl_xor_sync(0xffffffffu, sB, 1);
        sB += __shfl_xor_sync(0xffffffffu, sB, 2);
        lA = lA * cA + sA; lB = lB * cB + sB;
        mA = mAn; mB = mBn;
        #pragma unroll
        for (int nt = 0; nt < 8; nt++) {
            o[nt][0] *= cA; o[nt][1] *= cA;
            o[nt][2] *= cB; o[nt][3] *= cB;
        }

        // write P to p_s[row][key]
        #pragma unroll
        for (int nt = 0; nt < 8; nt++) {
            *(float2*)&p_s[(w16 + qr) * PPAD + nt * 8 + 2 * qc] = make_float2(s[nt][0], s[nt][1]);
            *(float2*)&p_s[(w16 + qr + 8) * PPAD + nt * 8 + 2 * qc] = make_float2(s[nt][2], s[nt][3]);
        }
        __syncwarp();

        // O += P V
        #pragma unroll
        for (int kj = 0; kj < 8; kj++) {
            float pa[4];
            pa[0] = p_s[(w16 + qr) * PPAD + kj * 8 + qc];
            pa[1] = p_s[(w16 + qr + 8) * PPAD + kj * 8 + qc];
            pa[2] = p_s[(w16 + qr) * PPAD + kj * 8 + qc + 4];
            pa[3] = p_s[(w16 + qr + 8) * PPAD + kj * 8 + qc + 4];
            #pragma unroll
            for (int nt = 0; nt < 8; nt++) {
                float b0 = v_s[(nt * 8 + qr) * VPAD + kj * 8 + qc];
                float b1 = v_s[(nt * 8 + qr) * VPAD + kj * 8 + qc + 4];
                mma_tf32(o[nt], pa, b0, b1);
            }
        }
    }

    // normalize, stage O as [d][i], coalesced store
    __syncthreads();
    float rA = 1.f / lA, rB = 1.f / lB;
    #pragma unroll
    for (int nt = 0; nt < 8; nt++) {
        p_s[(nt * 8 + 2 * qc) * QSTRIDE + w16 + qr]         = o[nt][0] * rA;
        p_s[(nt * 8 + 2 * qc + 1) * QSTRIDE + w16 + qr]     = o[nt][1] * rA;
        p_s[(nt * 8 + 2 * qc) * QSTRIDE + w16 + qr + 8]     = o[nt][2] * rB;
        p_s[(nt * 8 + 2 * qc + 1) * QSTRIDE + w16 + qr + 8] = o[nt][3] * rB;
    }
    __syncthreads();
    #pragma unroll
    for (int it = 0; it < 8; it++) {
        int idx = t + it * 256;
        int d = idx >> 5, i8 = idx & 31;
        *(float4*)&op[(size_t)d * SS + i0 + i8 * 4] = *(float4*)&p_s[d * QSTRIDE + i8 * 4];
    }
}

// ---------------- launch ----------------
extern "C" void kernel_launch(void* const* d_in, const int* in_sizes, int n_in,
                              void* d_out, int out_size) {
    const float* x    = (const float*)d_in[0];
    const float* gn_w = (const float*)d_in[1];
    const float* gn_b = (const float*)d_in[2];
    const float* wq   = (const float*)d_in[3];
    const float* wk   = (const float*)d_in[4];
    const float* wv   = (const float*)d_in[5];
    const float* wo   = (const float*)d_in[6];
    const float* bo   = (const float*)d_in[7];
    float* out = (float*)d_out;

    static int smem_set = 0;
    if (!smem_set) {
        cudaFuncSetAttribute(flash_mma_kernel, cudaFuncAttributeMaxDynamicSharedMemorySize,
                             SM_TOTAL_F * (int)sizeof(float));
        smem_set = 1;
    }

    // 1) GroupNorm
    gn_kernel<<<BB * NGROUPS, 256>>>(x, gn_w, gn_b);
    // 2) Q/K/V projections (tf32 tensor core)
    {
        dim3 grid(SS / 128, CC / 128, BB * 3);
        qkv_mm_kernel<<<grid, 256>>>(wq, wk, wv);
    }
    // 3) flash attention (tf32 tensor core)
    {
        dim3 grid(SS / 128, NHH, BB);
        flash_mma_kernel<<<grid, 256, SM_TOTAL_F * (int)sizeof(float)>>>();
    }
    // 4) output projection + bias + residual (tf32 tensor core)
    {
        dim3 grid(SS / 128, CC / 128, BB);
        proj_mm_kernel<<<grid, 256>>>(wo, bo, x, out);
    }
}